// round 11
// baseline (speedup 1.0000x reference)
#include <cuda_runtime.h>
#include <cstdint>
#include <cstddef>

// ============================================================================
// InteractionBlock (DimeNet-like), FP32, scalar-FFMA core (proven R7 math).
// Round 10: kernel fusion.
//   dualA_kernel : x-tile once -> x_ji (g_h) and x_kj
//   ygemm_kernel : x_kj-tile once -> 8 y-slabs
//   chain_kernel : h-tile once -> C,D,E1,E2,F (8 chained GEMMs in smem)
// ============================================================================

#define MAX_E 50000
#define MAX_T 200000

__device__ float g_rbfh[MAX_E * 128];
__device__ float g_xkj [MAX_E * 128];
__device__ float g_h   [MAX_E * 128];
__device__ float g_sbfh[MAX_T * 8];
__device__ float g_Wt  [8 * 128 * 128];     // Wt[j][k][n] = Wbil[n][j][k]
__device__ float g_y   [MAX_E * 1024];      // y[e][j*128+n]

__device__ __forceinline__ float silu_f(float v) {
    return v / (1.0f + __expf(-v));
}

__device__ __forceinline__ void cp_async16(void* smem_dst, const void* gl_src) {
    uint32_t s = (uint32_t)__cvta_generic_to_shared(smem_dst);
    asm volatile("cp.async.cg.shared.global [%0], [%1], 16;\n" :: "r"(s), "l"(gl_src));
}
__device__ __forceinline__ void cp_async_commit() {
    asm volatile("cp.async.commit_group;\n" ::: "memory");
}
__device__ __forceinline__ void cp_async_wait0() {
    asm volatile("cp.async.wait_group 0;\n" ::: "memory");
}

// ---------------------------------------------------------------------------
// Tiny prep kernels
// ---------------------------------------------------------------------------
__global__ void transpose_wbil(const float* __restrict__ Wbil) {
    int gid = blockIdx.x * blockDim.x + threadIdx.x;
    if (gid >= 8 * 128 * 128) return;
    int n = gid & 127;
    int k = (gid >> 7) & 127;
    int j = gid >> 14;
    g_Wt[gid] = Wbil[n * 1024 + j * 128 + k];
}

__global__ void rbfh_kernel(const float* __restrict__ rbf,
                            const float* __restrict__ Wrbf, int E) {
    int gid = blockIdx.x * blockDim.x + threadIdx.x;
    if (gid >= E * 128) return;
    int e = gid >> 7, n = gid & 127;
    float acc = 0.0f;
#pragma unroll
    for (int i = 0; i < 6; i++) acc += rbf[e * 6 + i] * Wrbf[i * 128 + n];
    g_rbfh[gid] = acc;
}

__global__ void sbfh_kernel(const float* __restrict__ sbf,
                            const float* __restrict__ Wsbf, int T) {
    int t = blockIdx.x * blockDim.x + threadIdx.x;
    if (t >= T) return;
    float acc[8];
#pragma unroll
    for (int j = 0; j < 8; j++) acc[j] = 0.0f;
    const float* row = sbf + (long)t * 42;
#pragma unroll
    for (int i = 0; i < 42; i++) {
        float s = row[i];
#pragma unroll
        for (int j = 0; j < 8; j++) acc[j] += s * Wsbf[i * 8 + j];
    }
    float4* o = (float4*)(g_sbfh + t * 8);
    o[0] = make_float4(acc[0], acc[1], acc[2], acc[3]);
    o[1] = make_float4(acc[4], acc[5], acc[6], acc[7]);
}

// ---------------------------------------------------------------------------
// Scalar inner compute: one BK=16 chunk (R3/R7 proven).
// As4: [64 rows][33 float4 stride], Wc4: [16 k][32 float4].
// ---------------------------------------------------------------------------
__device__ __forceinline__ void chunk_mma(const float4* __restrict__ As4,
                                          const float4* __restrict__ Wc4,
                                          int kt, int tmg, int tng,
                                          float acc[8][8]) {
#pragma unroll
    for (int k4 = 0; k4 < 4; k4++) {
        float4 b[4][2];
#pragma unroll
        for (int kk = 0; kk < 4; kk++) {
            b[kk][0] = Wc4[(k4 * 4 + kk) * 32 + tng * 2];
            b[kk][1] = Wc4[(k4 * 4 + kk) * 32 + tng * 2 + 1];
        }
#pragma unroll
        for (int i = 0; i < 8; i++) {
            float4 a = As4[(tmg * 8 + i) * 33 + kt * 4 + k4];
            float av[4] = {a.x, a.y, a.z, a.w};
#pragma unroll
            for (int kk = 0; kk < 4; kk++) {
                float f = av[kk];
                acc[i][0] += f * b[kk][0].x;
                acc[i][1] += f * b[kk][0].y;
                acc[i][2] += f * b[kk][0].z;
                acc[i][3] += f * b[kk][0].w;
                acc[i][4] += f * b[kk][1].x;
                acc[i][5] += f * b[kk][1].y;
                acc[i][6] += f * b[kk][1].z;
                acc[i][7] += f * b[kk][1].w;
            }
        }
    }
}

// ---------------------------------------------------------------------------
// Unified GEMM step.  In/Out are smem tiles (64 x 33 float4, k-major).
// Caller must __syncthreads() between steps.
// Modes:
//   0 SMEM_SILU      : Out = silu(acc+b)
//   1 SMEM_RESADD    : Out += silu(acc+b)        (Out is residual target)
//   2 SMEM_SILU_ADDG : Out = silu(acc+b) + Xg[row]
//   3 G_SILU         : Cg[row] = silu(acc+b)
//   4 G_SILU_MUL     : Cg[row] = silu(acc+b) * Xg[row]
//   5 G_PLAIN        : Cg[row] = acc
// ---------------------------------------------------------------------------
#define M_SMEM_SILU      0
#define M_SMEM_RESADD    1
#define M_SMEM_SILU_ADDG 2
#define M_G_SILU         3
#define M_G_SILU_MUL     4
#define M_G_PLAIN        5

template <int MODE>
__device__ __forceinline__ void gemm_step(
    const float4* __restrict__ In, float4* __restrict__ Out,
    float4* __restrict__ Wb4, const float4* __restrict__ Wg,
    const float* __restrict__ bias, const float* __restrict__ Xg,
    float4* __restrict__ Cg, int ld4,
    int brow, int M, int tid, int tmg, int tng)
{
    // W chunk 0
#pragma unroll
    for (int q = 0; q < 4; q++) {
        int i = q * 128 + tid;
        int wr = i >> 5, wc4 = i & 31;
        cp_async16(&Wb4[wr * 32 + wc4], &Wg[wr * 32 + wc4]);
    }
    cp_async_commit();
    cp_async_wait0();
    __syncthreads();

    float acc[8][8];
#pragma unroll
    for (int i = 0; i < 8; i++)
#pragma unroll
        for (int j = 0; j < 8; j++) acc[i][j] = 0.0f;

#pragma unroll 1
    for (int kt = 0; kt < 8; kt++) {
        if (kt < 7) {
            int nb = (kt + 1) & 1;
#pragma unroll
            for (int q = 0; q < 4; q++) {
                int i = q * 128 + tid;
                int wr = i >> 5, wc4 = i & 31;
                cp_async16(&Wb4[nb * 512 + wr * 32 + wc4],
                           &Wg[((kt + 1) * 16 + wr) * 32 + wc4]);
            }
            cp_async_commit();
        }
        chunk_mma(In, Wb4 + (kt & 1) * 512, kt, tmg, tng, acc);
        if (kt < 7) {
            cp_async_wait0();
            __syncthreads();
        }
    }

    float bc[8];
    if (MODE != M_G_PLAIN) {
#pragma unroll
        for (int j = 0; j < 8; j++) bc[j] = bias[tng * 8 + j];
    }

#pragma unroll
    for (int i = 0; i < 8; i++) {
        int row  = brow + tmg * 8 + i;
        bool valid = (row < M);
        float o[8];
#pragma unroll
        for (int j = 0; j < 8; j++)
            o[j] = (MODE == M_G_PLAIN) ? acc[i][j] : silu_f(acc[i][j] + bc[j]);

        if (MODE == M_SMEM_SILU || MODE == M_SMEM_RESADD || MODE == M_SMEM_SILU_ADDG) {
            int sidx = (tmg * 8 + i) * 33 + tng * 2;
            if (MODE == M_SMEM_RESADD) {
                float4 r0 = Out[sidx], r1 = Out[sidx + 1];
                Out[sidx]     = make_float4(r0.x + o[0], r0.y + o[1], r0.z + o[2], r0.w + o[3]);
                Out[sidx + 1] = make_float4(r1.x + o[4], r1.y + o[5], r1.z + o[6], r1.w + o[7]);
            } else if (MODE == M_SMEM_SILU_ADDG) {
                float4 e0 = make_float4(0.f, 0.f, 0.f, 0.f), e1 = e0;
                if (valid) {
                    e0 = ((const float4*)Xg)[(size_t)row * 32 + tng * 2];
                    e1 = ((const float4*)Xg)[(size_t)row * 32 + tng * 2 + 1];
                }
                Out[sidx]     = make_float4(o[0] + e0.x, o[1] + e0.y, o[2] + e0.z, o[3] + e0.w);
                Out[sidx + 1] = make_float4(o[4] + e1.x, o[5] + e1.y, o[6] + e1.z, o[7] + e1.w);
            } else {
                Out[sidx]     = make_float4(o[0], o[1], o[2], o[3]);
                Out[sidx + 1] = make_float4(o[4], o[5], o[6], o[7]);
            }
        } else {
            if (!valid) continue;
            if (MODE == M_G_SILU_MUL) {
                float4 e0 = ((const float4*)Xg)[(size_t)row * 32 + tng * 2];
                float4 e1 = ((const float4*)Xg)[(size_t)row * 32 + tng * 2 + 1];
                o[0] *= e0.x; o[1] *= e0.y; o[2] *= e0.z; o[3] *= e0.w;
                o[4] *= e1.x; o[5] *= e1.y; o[6] *= e1.z; o[7] *= e1.w;
            }
            Cg[(size_t)row * ld4 + tng * 2]     = make_float4(o[0], o[1], o[2], o[3]);
            Cg[(size_t)row * ld4 + tng * 2 + 1] = make_float4(o[4], o[5], o[6], o[7]);
        }
    }
}

// Tile loader: A[M,128] rows brow..brow+63 -> buf (64 x 33 float4), zero-pad.
__device__ __forceinline__ void load_tile(const float* __restrict__ A,
                                          float4* __restrict__ buf,
                                          int brow, int M, int tid) {
    const float4* Ag = (const float4*)A;
#pragma unroll
    for (int it = 0; it < 16; it++) {
        int i = it * 128 + tid;
        int r = i >> 5, c4 = i & 31;
        float4 v = make_float4(0.f, 0.f, 0.f, 0.f);
        if (brow + r < M) v = Ag[(size_t)(brow + r) * 32 + c4];
        buf[r * 33 + c4] = v;
    }
}

// smem sizes
#define SM1 ((64 * 132 + 2 * 16 * 128) * sizeof(float))              // 1 buf + Wb
#define SM2 ((2 * 64 * 132 + 2 * 16 * 128) * sizeof(float))          // 2 buf + Wb

// ---------------------------------------------------------------------------
// Stage A: h = silu(x@Wji+bji) ; xkj = silu(x@Wkj+bkj) * rbfh
// ---------------------------------------------------------------------------
__global__ void __launch_bounds__(128, 4)
dualA_kernel(const float* __restrict__ x,
             const float* __restrict__ Wji, const float* __restrict__ bji,
             const float* __restrict__ Wkj, const float* __restrict__ bkj,
             float* __restrict__ h, float* __restrict__ xkj, int M) {
    extern __shared__ float sm[];
    float4* buf0 = (float4*)sm;
    float4* Wb4  = (float4*)(sm + 64 * 132);
    const int tid = threadIdx.x, brow = blockIdx.x * 64;
    const int tmg = tid >> 4, tng = tid & 15;

    load_tile(x, buf0, brow, M, tid);
    __syncthreads();
    gemm_step<M_G_SILU>(buf0, nullptr, Wb4, (const float4*)Wji, bji,
                        nullptr, (float4*)h, 32, brow, M, tid, tmg, tng);
    __syncthreads();
    gemm_step<M_G_SILU_MUL>(buf0, nullptr, Wb4, (const float4*)Wkj, bkj,
                            g_rbfh, (float4*)xkj, 32, brow, M, tid, tmg, tng);
}

// ---------------------------------------------------------------------------
// Stage B1: y[e, j*128+n] = sum_k xkj[e,k] * Wt[j,k,n]
// ---------------------------------------------------------------------------
__global__ void __launch_bounds__(128, 4)
ygemm_kernel(const float* __restrict__ xkj, float* __restrict__ Y, int M) {
    extern __shared__ float sm[];
    float4* buf0 = (float4*)sm;
    float4* Wb4  = (float4*)(sm + 64 * 132);
    const int tid = threadIdx.x, brow = blockIdx.x * 64;
    const int tmg = tid >> 4, tng = tid & 15;

    load_tile(xkj, buf0, brow, M, tid);
    __syncthreads();
#pragma unroll 1
    for (int j = 0; j < 8; j++) {
        gemm_step<M_G_PLAIN>(buf0, nullptr, Wb4,
                             ((const float4*)g_Wt) + j * 4096, nullptr,
                             nullptr, ((float4*)Y) + j * 32, 256,
                             brow, M, tid, tmg, tng);
        __syncthreads();
    }
}

// ---------------------------------------------------------------------------
// Stage C..F chained: per 64-row tile, 8 GEMMs in smem.
// ---------------------------------------------------------------------------
__global__ void __launch_bounds__(128, 2)
chain_kernel(const float* __restrict__ h, const float* __restrict__ x,
             const float* __restrict__ bW1, const float* __restrict__ bb1,
             const float* __restrict__ bW2, const float* __restrict__ bb2,
             const float* __restrict__ Wlin, const float* __restrict__ blin,
             const float* __restrict__ aW1, const float* __restrict__ ab1,
             const float* __restrict__ aW2, const float* __restrict__ ab2,
             const float* __restrict__ Wout, const float* __restrict__ bout,
             float* __restrict__ out, int M) {
    extern __shared__ float sm[];
    float4* buf0 = (float4*)sm;
    float4* buf1 = (float4*)(sm + 64 * 132);
    float4* Wb4  = (float4*)(sm + 2 * 64 * 132);
    const int tid = threadIdx.x, brow = blockIdx.x * 64;
    const int tmg = tid >> 4, tng = tid & 15;

    load_tile(h, buf0, brow, M, tid);
    __syncthreads();

    // C: buf0 = h + silu(silu(h@bW1+bb1)@bW2+bb2)
    gemm_step<M_SMEM_SILU>(buf0, buf1, Wb4, (const float4*)bW1, bb1,
                           nullptr, nullptr, 0, brow, M, tid, tmg, tng);
    __syncthreads();
    gemm_step<M_SMEM_RESADD>(buf1, buf0, Wb4, (const float4*)bW2, bb2,
                             nullptr, nullptr, 0, brow, M, tid, tmg, tng);
    __syncthreads();
    // D: buf1 = silu(buf0@Wlin+blin) + x
    gemm_step<M_SMEM_SILU_ADDG>(buf0, buf1, Wb4, (const float4*)Wlin, blin,
                                x, nullptr, 0, brow, M, tid, tmg, tng);
    __syncthreads();
    // E1
    gemm_step<M_SMEM_SILU>(buf1, buf0, Wb4, (const float4*)aW1, ab1,
                           nullptr, nullptr, 0, brow, M, tid, tmg, tng);
    __syncthreads();
    gemm_step<M_SMEM_RESADD>(buf0, buf1, Wb4, (const float4*)aW2, ab2,
                             nullptr, nullptr, 0, brow, M, tid, tmg, tng);
    __syncthreads();
    // E2
    gemm_step<M_SMEM_SILU>(buf1, buf0, Wb4, (const float4*)(aW1 + 16384), ab1 + 128,
                           nullptr, nullptr, 0, brow, M, tid, tmg, tng);
    __syncthreads();
    gemm_step<M_SMEM_RESADD>(buf0, buf1, Wb4, (const float4*)(aW2 + 16384), ab2 + 128,
                             nullptr, nullptr, 0, brow, M, tid, tmg, tng);
    __syncthreads();
    // F
    gemm_step<M_G_SILU>(buf1, nullptr, Wb4, (const float4*)Wout, bout,
                        nullptr, (float4*)out, 32, brow, M, tid, tmg, tng);
}

// ---------------------------------------------------------------------------
// Combine + scatter: one warp per triplet.
// ---------------------------------------------------------------------------
__global__ void __launch_bounds__(256)
combine_kernel(const float* __restrict__ Y,
               const int* __restrict__ idx_kj, const int* __restrict__ idx_ji,
               float* __restrict__ h, int T) {
    int t = blockIdx.x * 8 + (threadIdx.x >> 5);
    if (t >= T) return;
    int lane = threadIdx.x & 31;

    int ekj = __ldg(&idx_kj[t]);
    int eji = __ldg(&idx_ji[t]);
    const float4* s4 = (const float4*)(g_sbfh + (size_t)t * 8);
    float4 sA = s4[0], sB = s4[1];
    float s[8] = {sA.x, sA.y, sA.z, sA.w, sB.x, sB.y, sB.z, sB.w};

    const float4* yr = (const float4*)(Y + (size_t)ekj * 1024);
    float4 acc = make_float4(0.f, 0.f, 0.f, 0.f);
#pragma unroll
    for (int j = 0; j < 8; j++) {
        float4 v = __ldg(&yr[j * 32 + lane]);
        acc.x += s[j] * v.x;
        acc.y += s[j] * v.y;
        acc.z += s[j] * v.z;
        acc.w += s[j] * v.w;
    }
    atomicAdd(&((float4*)h)[(size_t)eji * 32 + lane], acc);
}

// ---------------------------------------------------------------------------
// Host launcher
// ---------------------------------------------------------------------------
extern "C" void kernel_launch(void* const* d_in, const int* in_sizes, int n_in,
                              void* d_out, int out_size) {
    const float* x      = (const float*)d_in[0];
    const float* rbf    = (const float*)d_in[1];
    const float* sbf    = (const float*)d_in[2];
    const int*   idx_kj = (const int*)d_in[3];
    const int*   idx_ji = (const int*)d_in[4];
    const float* W_rbf  = (const float*)d_in[5];
    const float* W_sbf  = (const float*)d_in[6];
    const float* Wkj    = (const float*)d_in[7];
    const float* bkj    = (const float*)d_in[8];
    const float* Wji    = (const float*)d_in[9];
    const float* bji    = (const float*)d_in[10];
    const float* Wbil   = (const float*)d_in[11];
    const float* bW1    = (const float*)d_in[12];
    const float* bb1    = (const float*)d_in[13];
    const float* bW2    = (const float*)d_in[14];
    const float* bb2    = (const float*)d_in[15];
    const float* Wlin   = (const float*)d_in[16];
    const float* blin   = (const float*)d_in[17];
    const float* aW1    = (const float*)d_in[18];
    const float* ab1    = (const float*)d_in[19];
    const float* aW2    = (const float*)d_in[20];
    const float* ab2    = (const float*)d_in[21];
    const float* Wout   = (const float*)d_in[22];
    const float* bout   = (const float*)d_in[23];
    float* out = (float*)d_out;

    const int E = in_sizes[0] / 128;
    const int T = in_sizes[3];

    float *xkj, *h, *y;
    cudaGetSymbolAddress((void**)&xkj, g_xkj);
    cudaGetSymbolAddress((void**)&h,   g_h);
    cudaGetSymbolAddress((void**)&y,   g_y);

    cudaFuncSetAttribute(dualA_kernel, cudaFuncAttributeMaxDynamicSharedMemorySize, (int)SM1);
    cudaFuncSetAttribute(ygemm_kernel, cudaFuncAttributeMaxDynamicSharedMemorySize, (int)SM1);
    cudaFuncSetAttribute(chain_kernel, cudaFuncAttributeMaxDynamicSharedMemorySize, (int)SM2);

    // Stage 0: tiny preps
    transpose_wbil<<<(8 * 128 * 128 + 255) / 256, 256>>>(Wbil);
    rbfh_kernel<<<(E * 128 + 255) / 256, 256>>>(rbf, W_rbf, E);
    sbfh_kernel<<<(T + 255) / 256, 256>>>(sbf, W_sbf, T);

    const int gE = (E + 63) / 64;

    // Stage A (fused): h = silu(x@Wji+bji), xkj = silu(x@Wkj+bkj)*rbfh
    dualA_kernel<<<gE, 128, SM1>>>(x, Wji, bji, Wkj, bkj, h, xkj, E);

    // Stage B1: per-edge bilinear precompute y
    ygemm_kernel<<<gE, 128, SM1>>>(xkj, y, E);

    // Stage B2: per-triplet combine + scatter into h => h = x_ji + agg
    combine_kernel<<<(T + 7) / 8, 256>>>(y, idx_kj, idx_ji, h, T);

    // Stages C..F (fused chain) -> out
    chain_kernel<<<gE, 128, SM2>>>(h, x, bW1, bb1, bW2, bb2, Wlin, blin,
                                   aW1, ab1, aW2, ab2, Wout, bout, out, E);
}

// round 12
// speedup vs baseline: 1.5899x; 1.5899x over previous
#include <cuda_runtime.h>
#include <cstdint>
#include <cstddef>

// ============================================================================
// InteractionBlock (DimeNet-like). H = 128 fixed.
// Round 11: TF32 tensor-core GEMM core (mma.sync.m16n8k8.tf32, fp32 accum).
// Structure: dualA (x->h, x->xkj) ; ygemm (xkj -> 8 y-slabs, A-tile reused) ;
// combine (gather/weighted-sum/scatter) ; 8 single GEMMs for C..F.
// ============================================================================

#define MAX_E 50000
#define MAX_T 200000

__device__ float g_rbfh[MAX_E * 128];
__device__ float g_xkj [MAX_E * 128];
__device__ float g_h   [MAX_E * 128];
__device__ float g_tmp [MAX_E * 128];
__device__ float g_sbfh[MAX_T * 8];
__device__ float g_Wt  [8 * 128 * 128];     // Wt[j][k][n] = Wbil[n][j][k]
__device__ float g_y   [MAX_E * 1024];      // y[e][j*128+n]

__device__ __forceinline__ float silu_f(float v) {
    return v / (1.0f + __expf(-v));
}

__device__ __forceinline__ uint32_t f2tf32(float f) {
    uint32_t u;
    asm("cvt.rna.tf32.f32 %0, %1;" : "=r"(u) : "f"(f));
    return u;
}

__device__ __forceinline__ void mma_tf32(float c[4],
                                         uint32_t a0, uint32_t a1,
                                         uint32_t a2, uint32_t a3,
                                         uint32_t b0, uint32_t b1) {
    asm("mma.sync.aligned.m16n8k8.row.col.f32.tf32.tf32.f32 "
        "{%0,%1,%2,%3}, {%4,%5,%6,%7}, {%8,%9}, {%0,%1,%2,%3};"
        : "+f"(c[0]), "+f"(c[1]), "+f"(c[2]), "+f"(c[3])
        : "r"(a0), "r"(a1), "r"(a2), "r"(a3), "r"(b0), "r"(b1));
}

// ---------------------------------------------------------------------------
// Tiny prep kernels
// ---------------------------------------------------------------------------
__global__ void transpose_wbil(const float* __restrict__ Wbil) {
    int gid = blockIdx.x * blockDim.x + threadIdx.x;
    if (gid >= 8 * 128 * 128) return;
    int n = gid & 127;
    int k = (gid >> 7) & 127;
    int j = gid >> 14;
    g_Wt[gid] = Wbil[n * 1024 + j * 128 + k];
}

__global__ void rbfh_kernel(const float* __restrict__ rbf,
                            const float* __restrict__ Wrbf, int E) {
    int gid = blockIdx.x * blockDim.x + threadIdx.x;
    if (gid >= E * 128) return;
    int e = gid >> 7, n = gid & 127;
    float acc = 0.0f;
#pragma unroll
    for (int i = 0; i < 6; i++) acc += rbf[e * 6 + i] * Wrbf[i * 128 + n];
    g_rbfh[gid] = acc;
}

__global__ void sbfh_kernel(const float* __restrict__ sbf,
                            const float* __restrict__ Wsbf, int T) {
    int t = blockIdx.x * blockDim.x + threadIdx.x;
    if (t >= T) return;
    float acc[8];
#pragma unroll
    for (int j = 0; j < 8; j++) acc[j] = 0.0f;
    const float* row = sbf + (long)t * 42;
#pragma unroll
    for (int i = 0; i < 42; i++) {
        float s = row[i];
#pragma unroll
        for (int j = 0; j < 8; j++) acc[j] += s * Wsbf[i * 8 + j];
    }
    float4* o = (float4*)(g_sbfh + t * 8);
    o[0] = make_float4(acc[0], acc[1], acc[2], acc[3]);
    o[1] = make_float4(acc[4], acc[5], acc[6], acc[7]);
}

// ---------------------------------------------------------------------------
// TF32 GEMM building blocks.
// smem layout (uint32): As[64][132], Ws[128][132].   101376 bytes total.
// Block = 128 threads (4 warps in 2x2 grid), tile 64(M) x 128(N), K=128.
// Warp tile 32x64: 2 m16-tiles x 8 n8-tiles, 16 k-steps of k8.
// ---------------------------------------------------------------------------
#define AS_LD 132
#define SMEM_TF32 ((64 * AS_LD + 128 * AS_LD) * 4)

__device__ __forceinline__ void load_convert_A(const float* __restrict__ A,
                                               uint32_t* __restrict__ As,
                                               int brow, int M, int tid) {
    const float4* Ag = (const float4*)A;
#pragma unroll
    for (int it = 0; it < 16; it++) {
        int i = it * 128 + tid;
        int r = i >> 5, c4 = i & 31;
        float4 v = make_float4(0.f, 0.f, 0.f, 0.f);
        if (brow + r < M) v = Ag[(size_t)(brow + r) * 32 + c4];
        uint4 t;
        t.x = f2tf32(v.x); t.y = f2tf32(v.y);
        t.z = f2tf32(v.z); t.w = f2tf32(v.w);
        *(uint4*)&As[r * AS_LD + c4 * 4] = t;
    }
}

__device__ __forceinline__ void load_convert_W(const float* __restrict__ W,
                                               uint32_t* __restrict__ Ws,
                                               int tid) {
    const float4* Wg = (const float4*)W;
#pragma unroll
    for (int it = 0; it < 32; it++) {
        int i = it * 128 + tid;
        int r = i >> 5, c4 = i & 31;
        float4 v = Wg[r * 32 + c4];
        uint4 t;
        t.x = f2tf32(v.x); t.y = f2tf32(v.y);
        t.z = f2tf32(v.z); t.w = f2tf32(v.w);
        *(uint4*)&Ws[r * AS_LD + c4 * 4] = t;
    }
}

// acc[mt][nt][4]
__device__ __forceinline__ void compute_tf32(const uint32_t* __restrict__ As,
                                             const uint32_t* __restrict__ Ws,
                                             int warp_m, int warp_n,
                                             int gid, int tig,
                                             float acc[2][8][4]) {
#pragma unroll
    for (int mt = 0; mt < 2; mt++)
#pragma unroll
        for (int nt = 0; nt < 8; nt++)
#pragma unroll
            for (int c = 0; c < 4; c++) acc[mt][nt][c] = 0.0f;

#pragma unroll 2
    for (int ks = 0; ks < 16; ks++) {
        int kb = ks * 8;
        uint32_t a[2][4];
#pragma unroll
        for (int mt = 0; mt < 2; mt++) {
            int r0 = warp_m * 32 + mt * 16 + gid;
            a[mt][0] = As[r0 * AS_LD + kb + tig];
            a[mt][1] = As[(r0 + 8) * AS_LD + kb + tig];
            a[mt][2] = As[r0 * AS_LD + kb + tig + 4];
            a[mt][3] = As[(r0 + 8) * AS_LD + kb + tig + 4];
        }
        uint32_t b[8][2];
#pragma unroll
        for (int nt = 0; nt < 8; nt++) {
            int n = warp_n * 64 + nt * 8 + gid;
            b[nt][0] = Ws[(kb + tig) * AS_LD + n];
            b[nt][1] = Ws[(kb + tig + 4) * AS_LD + n];
        }
#pragma unroll
        for (int mt = 0; mt < 2; mt++)
#pragma unroll
            for (int nt = 0; nt < 8; nt++)
                mma_tf32(acc[mt][nt], a[mt][0], a[mt][1], a[mt][2], a[mt][3],
                         b[nt][0], b[nt][1]);
    }
}

// Epilogue modes
#define M_SILU     0   // C = silu(acc + b)
#define M_SILU_MUL 1   // C = silu(acc + b) * extra[row]
#define M_SILU_ADD 2   // C = silu(acc + b) + extra[row]
#define M_PLAIN    3   // C = acc

template <int MODE>
__device__ __forceinline__ void epilogue_tf32(const float acc[2][8][4],
                                              const float* __restrict__ bias,
                                              const float* __restrict__ extra,
                                              float* __restrict__ Cg, int ldc,
                                              int brow, int M,
                                              int warp_m, int warp_n,
                                              int gid, int tig) {
#pragma unroll
    for (int mt = 0; mt < 2; mt++) {
        int rbase = brow + warp_m * 32 + mt * 16 + gid;
#pragma unroll
        for (int half = 0; half < 2; half++) {      // c0/c1 then c2/c3
            int row = rbase + half * 8;
            if (row >= M) continue;
#pragma unroll
            for (int nt = 0; nt < 8; nt++) {
                int n = warp_n * 64 + nt * 8 + tig * 2;
                float v0 = acc[mt][nt][half * 2];
                float v1 = acc[mt][nt][half * 2 + 1];
                if (MODE != M_PLAIN) {
                    v0 = silu_f(v0 + bias[n]);
                    v1 = silu_f(v1 + bias[n + 1]);
                }
                if (MODE == M_SILU_MUL) {
                    float2 e = *(const float2*)&extra[(size_t)row * 128 + n];
                    v0 *= e.x; v1 *= e.y;
                } else if (MODE == M_SILU_ADD) {
                    float2 e = *(const float2*)&extra[(size_t)row * 128 + n];
                    v0 += e.x; v1 += e.y;
                }
                float2 st; st.x = v0; st.y = v1;
                *(float2*)&Cg[(size_t)row * ldc + n] = st;
            }
        }
    }
}

// ---------------------------------------------------------------------------
// Generic single GEMM: C[M, ldc-submatrix 128 cols] = mode(A@W + b)
// ---------------------------------------------------------------------------
template <int MODE>
__global__ void __launch_bounds__(128)
tf32_gemm(const float* __restrict__ A, const float* __restrict__ W,
          const float* __restrict__ bias, const float* __restrict__ extra,
          float* __restrict__ C, int ldc, int M) {
    extern __shared__ uint32_t smu[];
    uint32_t* As = smu;
    uint32_t* Ws = smu + 64 * AS_LD;
    const int tid = threadIdx.x, brow = blockIdx.x * 64;
    const int warp = tid >> 5, lane = tid & 31;
    const int warp_m = warp >> 1, warp_n = warp & 1;
    const int gid = lane >> 2, tig = lane & 3;

    load_convert_A(A, As, brow, M, tid);
    load_convert_W(W, Ws, tid);
    __syncthreads();

    float acc[2][8][4];
    compute_tf32(As, Ws, warp_m, warp_n, gid, tig, acc);
    epilogue_tf32<MODE>(acc, bias, extra, C, ldc, brow, M, warp_m, warp_n, gid, tig);
}

// ---------------------------------------------------------------------------
// Stage A fused: h = silu(x@Wji+bji) ; xkj = silu(x@Wkj+bkj) * rbfh
// ---------------------------------------------------------------------------
__global__ void __launch_bounds__(128)
dualA_tf32(const float* __restrict__ x,
           const float* __restrict__ Wji, const float* __restrict__ bji,
           const float* __restrict__ Wkj, const float* __restrict__ bkj,
           float* __restrict__ h, float* __restrict__ xkj, int M) {
    extern __shared__ uint32_t smu[];
    uint32_t* As = smu;
    uint32_t* Ws = smu + 64 * AS_LD;
    const int tid = threadIdx.x, brow = blockIdx.x * 64;
    const int warp = tid >> 5, lane = tid & 31;
    const int warp_m = warp >> 1, warp_n = warp & 1;
    const int gid = lane >> 2, tig = lane & 3;

    load_convert_A(x, As, brow, M, tid);

    load_convert_W(Wji, Ws, tid);
    __syncthreads();
    {
        float acc[2][8][4];
        compute_tf32(As, Ws, warp_m, warp_n, gid, tig, acc);
        epilogue_tf32<M_SILU>(acc, bji, nullptr, h, 128, brow, M,
                              warp_m, warp_n, gid, tig);
    }
    __syncthreads();   // all Ws reads done before overwrite

    load_convert_W(Wkj, Ws, tid);
    __syncthreads();
    {
        float acc[2][8][4];
        compute_tf32(As, Ws, warp_m, warp_n, gid, tig, acc);
        epilogue_tf32<M_SILU_MUL>(acc, bkj, g_rbfh, xkj, 128, brow, M,
                                  warp_m, warp_n, gid, tig);
    }
}

// ---------------------------------------------------------------------------
// Stage B1: y[e, j*128+n] = sum_k xkj[e,k]*Wt[j,k,n] — A-tile reused over j.
// ---------------------------------------------------------------------------
__global__ void __launch_bounds__(128)
ygemm_tf32(const float* __restrict__ xkj, float* __restrict__ Y, int M) {
    extern __shared__ uint32_t smu[];
    uint32_t* As = smu;
    uint32_t* Ws = smu + 64 * AS_LD;
    const int tid = threadIdx.x, brow = blockIdx.x * 64;
    const int warp = tid >> 5, lane = tid & 31;
    const int warp_m = warp >> 1, warp_n = warp & 1;
    const int gid = lane >> 2, tig = lane & 3;

    load_convert_A(xkj, As, brow, M, tid);

#pragma unroll 1
    for (int j = 0; j < 8; j++) {
        load_convert_W(g_Wt + j * 16384, Ws, tid);
        __syncthreads();
        float acc[2][8][4];
        compute_tf32(As, Ws, warp_m, warp_n, gid, tig, acc);
        epilogue_tf32<M_PLAIN>(acc, nullptr, nullptr, Y + j * 128, 1024,
                               brow, M, warp_m, warp_n, gid, tig);
        __syncthreads();   // Ws reads done before next j overwrites
    }
}

// ---------------------------------------------------------------------------
// Combine + scatter: one warp per triplet.
// ---------------------------------------------------------------------------
__global__ void __launch_bounds__(256)
combine_kernel(const float* __restrict__ Y,
               const int* __restrict__ idx_kj, const int* __restrict__ idx_ji,
               float* __restrict__ h, int T) {
    int t = blockIdx.x * 8 + (threadIdx.x >> 5);
    if (t >= T) return;
    int lane = threadIdx.x & 31;

    int ekj = __ldg(&idx_kj[t]);
    int eji = __ldg(&idx_ji[t]);
    const float4* s4 = (const float4*)(g_sbfh + (size_t)t * 8);
    float4 sA = s4[0], sB = s4[1];
    float s[8] = {sA.x, sA.y, sA.z, sA.w, sB.x, sB.y, sB.z, sB.w};

    const float4* yr = (const float4*)(Y + (size_t)ekj * 1024);
    float4 acc = make_float4(0.f, 0.f, 0.f, 0.f);
#pragma unroll
    for (int j = 0; j < 8; j++) {
        float4 v = __ldg(&yr[j * 32 + lane]);
        acc.x += s[j] * v.x;
        acc.y += s[j] * v.y;
        acc.z += s[j] * v.z;
        acc.w += s[j] * v.w;
    }
    atomicAdd(&((float4*)h)[(size_t)eji * 32 + lane], acc);
}

// ---------------------------------------------------------------------------
// Host launcher
// ---------------------------------------------------------------------------
extern "C" void kernel_launch(void* const* d_in, const int* in_sizes, int n_in,
                              void* d_out, int out_size) {
    const float* x      = (const float*)d_in[0];
    const float* rbf    = (const float*)d_in[1];
    const float* sbf    = (const float*)d_in[2];
    const int*   idx_kj = (const int*)d_in[3];
    const int*   idx_ji = (const int*)d_in[4];
    const float* W_rbf  = (const float*)d_in[5];
    const float* W_sbf  = (const float*)d_in[6];
    const float* Wkj    = (const float*)d_in[7];
    const float* bkj    = (const float*)d_in[8];
    const float* Wji    = (const float*)d_in[9];
    const float* bji    = (const float*)d_in[10];
    const float* Wbil   = (const float*)d_in[11];
    const float* bW1    = (const float*)d_in[12];
    const float* bb1    = (const float*)d_in[13];
    const float* bW2    = (const float*)d_in[14];
    const float* bb2    = (const float*)d_in[15];
    const float* Wlin   = (const float*)d_in[16];
    const float* blin   = (const float*)d_in[17];
    const float* aW1    = (const float*)d_in[18];
    const float* ab1    = (const float*)d_in[19];
    const float* aW2    = (const float*)d_in[20];
    const float* ab2    = (const float*)d_in[21];
    const float* Wout   = (const float*)d_in[22];
    const float* bout   = (const float*)d_in[23];
    float* out = (float*)d_out;

    const int E = in_sizes[0] / 128;
    const int T = in_sizes[3];

    float *xkj, *h, *tmp, *y;
    cudaGetSymbolAddress((void**)&xkj, g_xkj);
    cudaGetSymbolAddress((void**)&h,   g_h);
    cudaGetSymbolAddress((void**)&tmp, g_tmp);
    cudaGetSymbolAddress((void**)&y,   g_y);

    cudaFuncSetAttribute(tf32_gemm<M_SILU>,     cudaFuncAttributeMaxDynamicSharedMemorySize, SMEM_TF32);
    cudaFuncSetAttribute(tf32_gemm<M_SILU_ADD>, cudaFuncAttributeMaxDynamicSharedMemorySize, SMEM_TF32);
    cudaFuncSetAttribute(dualA_tf32,            cudaFuncAttributeMaxDynamicSharedMemorySize, SMEM_TF32);
    cudaFuncSetAttribute(ygemm_tf32,            cudaFuncAttributeMaxDynamicSharedMemorySize, SMEM_TF32);

    // Stage 0: tiny preps
    transpose_wbil<<<(8 * 128 * 128 + 255) / 256, 256>>>(Wbil);
    rbfh_kernel<<<(E * 128 + 255) / 256, 256>>>(rbf, W_rbf, E);
    sbfh_kernel<<<(T + 255) / 256, 256>>>(sbf, W_sbf, T);

    const int gE = (E + 63) / 64;

    // Stage A: h = silu(x@Wji+bji) ; xkj = silu(x@Wkj+bkj)*rbfh
    dualA_tf32<<<gE, 128, SMEM_TF32>>>(x, Wji, bji, Wkj, bkj, h, xkj, E);

    // Stage B1: y precompute
    ygemm_tf32<<<gE, 128, SMEM_TF32>>>(xkj, y, E);

    // Stage B2: combine + scatter into h  => h = x_ji + agg
    combine_kernel<<<(T + 7) / 8, 256>>>(y, idx_kj, idx_ji, h, T);

    // Stage C: h += silu(silu(h@bW1+bb1)@bW2+bb2)
    tf32_gemm<M_SILU><<<gE, 128, SMEM_TF32>>>(h,   bW1, bb1, nullptr, tmp, 128, E);
    tf32_gemm<M_SILU_ADD><<<gE, 128, SMEM_TF32>>>(tmp, bW2, bb2, h,    h,   128, E);

    // Stage D: h = silu(h@Wlin+blin) + x
    tf32_gemm<M_SILU_ADD><<<gE, 128, SMEM_TF32>>>(h, Wlin, blin, x, h, 128, E);

    // Stage E: after-skip MLP (2x)
    for (int i = 0; i < 2; i++) {
        tf32_gemm<M_SILU><<<gE, 128, SMEM_TF32>>>(h, aW1 + i * 16384, ab1 + i * 128,
                                                  nullptr, tmp, 128, E);
        tf32_gemm<M_SILU_ADD><<<gE, 128, SMEM_TF32>>>(tmp, aW2 + i * 16384, ab2 + i * 128,
                                                      h, h, 128, E);
    }

    // Stage F: out = silu(h@Wout+bout)
    tf32_gemm<M_SILU><<<gE, 128, SMEM_TF32>>>(h, Wout, bout, nullptr, out, 128, E);
}